// round 14
// baseline (speedup 1.0000x reference)
#include <cuda_runtime.h>
#include <cuda_bf16.h>
#include <cstdint>

// PointPillars BEV scatter, inverted as a gather (R9 chassis + STG.256 stage2).
//   1) cudaMemsetAsync grid to 0xFF (-1)
//   2) scatter pillar ids into grid[(b*H+y)*W+x]
//   3) persistent gather blocks (3/SM), double-buffered smem tile, ONE barrier
//      per tile, 4-slot idx+oct-flag ring prefetched 2 tiles ahead.
//      All-empty 8-cell octs (~30%) bypass smem in both directions.
//      Stage 2: 2x LDS.128 + 1x STG.256 per channel (256-bit stores).
#define BEV_H 496
#define BEV_W 432
#define BB    4
#define CC    64
#define GRID_CELLS (BB * BEV_H * BEV_W)   // 857088
#define TILE_X 128
#define NO     (TILE_X / 8)               // 16 octs per tile
#define NT     (BB * BEV_H * 4)           // 7936 tiles
#define ROW_STRIDE 132
#define TILE_FLOATS (CC * ROW_STRIDE)     // 8448 floats
#define GATHER_BLOCKS 456                 // 3 per SM on 152-SM GB300
#define SMEM_BYTES (2 * TILE_FLOATS * 4 + 4 * TILE_X * 4 + 4 * NO * 4)

__device__ int g_grid[GRID_CELLS];

__global__ void scatter_ids_kernel(const int* __restrict__ coords, int M) {
    int m = blockIdx.x * blockDim.x + threadIdx.x;
    if (m < M) {
        int b = coords[3 * m + 0];
        int y = coords[3 * m + 1];
        int x = coords[3 * m + 2];
        g_grid[(b * BEV_H + y) * BEV_W + x] = m;
    }
}

__device__ __forceinline__ void stg256_cs(float* ptr, const float4& a, const float4& b) {
    asm volatile(
        "st.global.cs.v8.b32 [%0], {%1,%2,%3,%4,%5,%6,%7,%8};"
        :: "l"(ptr),
           "r"(__float_as_uint(a.x)), "r"(__float_as_uint(a.y)),
           "r"(__float_as_uint(a.z)), "r"(__float_as_uint(a.w)),
           "r"(__float_as_uint(b.x)), "r"(__float_as_uint(b.y)),
           "r"(__float_as_uint(b.z)), "r"(__float_as_uint(b.w))
        : "memory");
}

__global__ __launch_bounds__(512, 3) void gather_kernel(
    const float* __restrict__ feat, float* __restrict__ out)
{
    extern __shared__ __align__(16) float smem[];
    float* vbuf  = smem;                                   // [2][TILE_FLOATS]
    int*   sring = (int*)(smem + 2 * TILE_FLOATS);         // [4][TILE_X]
    int*   oring = (int*)(smem + 2 * TILE_FLOATS + 4 * TILE_X);  // [4][NO] 1=empty

    const int tid   = threadIdx.x;
    const int p     = tid & 15;        // stage1: channel quad (c = 4p+j)
    const int rbase = tid >> 4;        // stage1: cell sub-index (0..31)
    const int xo    = tid & 15;        // stage2: x oct (8 cells)
    const int ch    = tid >> 4;        // stage2: channel (c in {ch, ch+32})

    const int step = gridDim.x;
    const int t0   = blockIdx.x;
    const size_t plane = (size_t)BEV_H * BEV_W;
    const float4* feat4 = reinterpret_cast<const float4*>(feat);

    // ---- index + oct-flag loader: one warp ----
    auto load_idx = [&](int t, int slot) {
        if (tid < 32) {
            int r  = t >> 2;
            int x0 = (t & 3) * TILE_X + 4 * tid;
            int base = r * BEV_W;
            int4 v;
            v.x = (x0 + 0 < BEV_W) ? __ldg(&g_grid[base + x0 + 0]) : -1;
            v.y = (x0 + 1 < BEV_W) ? __ldg(&g_grid[base + x0 + 1]) : -1;
            v.z = (x0 + 2 < BEV_W) ? __ldg(&g_grid[base + x0 + 2]) : -1;
            v.w = (x0 + 3 < BEV_W) ? __ldg(&g_grid[base + x0 + 3]) : -1;
            *reinterpret_cast<int4*>(&sring[slot * TILE_X + 4 * tid]) = v;
            bool qe = ((v.x & v.y & v.z & v.w) < 0);       // quad empty
            unsigned mask = __ballot_sync(0xffffffffu, qe);
            if (tid < NO)
                oring[slot * NO + tid] = (((mask >> (2 * tid)) & 3u) == 3u) ? 1 : 0;
        }
    };

    // ---- per-cell branchy gather: empty cell -> zero, no load ----
    auto gather = [&](int slot, float4* dst) {
#pragma unroll
        for (int i = 0; i < 4; i++) {
            int idx = sring[slot * TILE_X + i * 32 + rbase];
            float4 w = make_float4(0.f, 0.f, 0.f, 0.f);
            if (idx >= 0) {
                w = __ldg(feat4 + (size_t)idx * (CC / 4) + p);
            }
            dst[i] = w;
        }
    };

    float4 v[4];

    // ---- prologue ----
    load_idx(t0, 0);
    if (t0 + step < NT) load_idx(t0 + step, 1);
    __syncthreads();
    gather(0, v);

    int k = 0;
    for (int t = t0; t < NT; t += step, k++) {
        const int slot = k & 3;
        float* wb = vbuf + (size_t)(k & 1) * TILE_FLOATS;

        // Stage 1: STS only for cells in nonempty octs.
        // pos(x, c) = x ^ ((((c>>3) + (x>>5)) & 7) << 2); here c>>3 = p>>1, x>>5 = i.
#pragma unroll
        for (int i = 0; i < 4; i++) {
            int rl = i * 32 + rbase;
            if (!oring[slot * NO + (rl >> 3)]) {
                int kk = (((p >> 1) + i) & 7) << 2;
                int rx = rl ^ kk;
                wb[(4 * p + 0) * ROW_STRIDE + rx] = v[i].x;
                wb[(4 * p + 1) * ROW_STRIDE + rx] = v[i].y;
                wb[(4 * p + 2) * ROW_STRIDE + rx] = v[i].z;
                wb[(4 * p + 3) * ROW_STRIDE + rx] = v[i].w;
            }
        }

        // Prefetch indices 2 tiles ahead; gather features for next tile
        // (LDGs stay in flight across the barrier + store phase).
        if (t + 2 * step < NT) load_idx(t + 2 * step, (k + 2) & 3);
        if (t + step < NT)     gather((k + 1) & 3, v);

        __syncthreads();

        // Stage 2: per thread, 2 channels x 8 x-cells: 2x LDS.128 + 1x STG.256.
        {
            int r  = t >> 2;
            int b  = r / BEV_H;
            int y  = r - b * BEV_H;
            int x0 = (t & 3) * TILE_X + 8 * xo;   // octs never straddle W=432
            if (x0 < BEV_W) {
                const bool oe = (oring[slot * NO + xo] != 0);
                const float* rb = vbuf + (size_t)(k & 1) * TILE_FLOATS;
                const int xl = 8 * xo;            // tile-local x
                size_t gbase = ((size_t)(b * CC) * BEV_H + 0) * 0;  // (unused)
#pragma unroll
                for (int h = 0; h < 2; h++) {
                    int c  = ch + 32 * h;
                    float4 lo = make_float4(0.f, 0.f, 0.f, 0.f);
                    float4 hi = make_float4(0.f, 0.f, 0.f, 0.f);
                    if (!oe) {
                        int kk = (((c >> 3) + (xo >> 2)) & 7) << 2;
                        lo = *reinterpret_cast<const float4*>(
                            &rb[c * ROW_STRIDE + (xl ^ kk)]);
                        hi = *reinterpret_cast<const float4*>(
                            &rb[c * ROW_STRIDE + ((xl + 4) ^ kk)]);
                    }
                    float* gp = out + ((size_t)(b * CC + c) * BEV_H + y) * BEV_W + x0;
                    stg256_cs(gp, lo, hi);
                }
                (void)gbase;
            }
        }
        // Ring safety with one barrier: in window (bar k, bar k+1) readers use
        // slots {k, k+1, k+2} mod 4; the only writer uses slot k+3 mod 4.
    }
}

extern "C" void kernel_launch(void* const* d_in, const int* in_sizes, int n_in,
                              void* d_out, int out_size)
{
    const int*   coords = (const int*)d_in[0];    // (M, 3) int32 [b, y, x]
    const float* feat   = (const float*)d_in[1];  // (M, 64) float32
    float*       out    = (float*)d_out;          // (4, 64, 496, 432) float32

    const int M = in_sizes[0] / 3;

    void* grid_ptr = nullptr;
    cudaGetSymbolAddress(&grid_ptr, g_grid);
    cudaMemsetAsync(grid_ptr, 0xFF, GRID_CELLS * sizeof(int));  // all cells = -1

    scatter_ids_kernel<<<(M + 255) / 256, 256>>>(coords, M);

    static bool attr_set = false;
    if (!attr_set) {
        cudaFuncSetAttribute(gather_kernel,
                             cudaFuncAttributeMaxDynamicSharedMemorySize,
                             SMEM_BYTES);
        attr_set = true;
    }
    gather_kernel<<<GATHER_BLOCKS, 512, SMEM_BYTES>>>(feat, out);
}

// round 15
// speedup vs baseline: 1.8146x; 1.8146x over previous
#include <cuda_runtime.h>
#include <cuda_bf16.h>

// PointPillars BEV scatter, inverted as a gather (R9 chassis + uint16 grid).
//   1) cudaMemsetAsync grid16 to 0xFFFF (empty)
//   2) scatter batch-local pillar ids (16-bit) into grid16[(b*H+y)*W+x]
//   3) persistent gather blocks (3/SM), double-buffered smem tile, ONE barrier
//      per tile, 4-slot idx+flag ring prefetched 2 tiles ahead.
//      All-empty 4-cell quads (55%) bypass smem in BOTH directions.
#define BEV_H 496
#define BEV_W 432
#define BB    4
#define CC    64
#define GRID_CELLS (BB * BEV_H * BEV_W)   // 857088
#define TILE_X 128
#define NQ     (TILE_X / 4)               // 32 quads per tile
#define NT     (BB * BEV_H * 4)           // 7936 tiles (4 x-tiles per row)
#define ROW_STRIDE 132
#define TILE_FLOATS (CC * ROW_STRIDE)     // 8448 floats = 33792 B
#define GATHER_BLOCKS 456                 // 3 per SM on 152-SM GB300
// 2 tile buffers + 4-slot idx ring + 4-slot quad-flag ring
#define SMEM_BYTES (2 * TILE_FLOATS * 4 + 4 * TILE_X * 4 + 4 * NQ * 4)

__device__ unsigned short g_grid16[GRID_CELLS];   // 1.71 MB, L2-resident

__global__ void scatter_ids_kernel(const int* __restrict__ coords, int M, int mper) {
    int m = blockIdx.x * blockDim.x + threadIdx.x;
    if (m < M) {
        int b = coords[3 * m + 0];
        int y = coords[3 * m + 1];
        int x = coords[3 * m + 2];
        g_grid16[(b * BEV_H + y) * BEV_W + x] = (unsigned short)(m - b * mper);
    }
}

__global__ __launch_bounds__(512, 3) void gather_kernel(
    const float* __restrict__ feat, float* __restrict__ out, int mper)
{
    extern __shared__ __align__(16) float smem[];
    float* vbuf  = smem;                                   // [2][TILE_FLOATS]
    int*   sring = (int*)(smem + 2 * TILE_FLOATS);         // [4][TILE_X]
    int*   qring = (int*)(smem + 2 * TILE_FLOATS + 4 * TILE_X);  // [4][NQ] 1=empty

    const int tid   = threadIdx.x;
    const int p     = tid & 15;        // gather: channel quad
    const int rbase = tid >> 4;        // gather: cell sub-index (0..31)
    const int s4p   = (p >> 1) << 2;   // smem swizzle key for writes
    const int xq    = tid & 31;        // stage2: x quad
    const int cq    = tid >> 5;        // stage2: channel quad (0..15)

    const int step = gridDim.x;
    const int t0   = blockIdx.x;
    const size_t plane = (size_t)BEV_H * BEV_W;
    const float4* feat4 = reinterpret_cast<const float4*>(feat);

    // ---- index + quad-flag loader: one warp; ushort4 grid reads ----
    auto load_idx = [&](int t, int slot) {
        if (tid < 32) {
            int r  = t >> 2;                   // combined b*H + y
            int b  = r / BEV_H;
            int x0 = (t & 3) * TILE_X + 4 * tid;
            int base = r * BEV_W;
            int fbase = b * mper;
            int e0 = -1, e1 = -1, e2 = -1, e3 = -1;
            if (x0 + 3 < BEV_W) {
                ushort4 u = __ldg(reinterpret_cast<const ushort4*>(&g_grid16[base + x0]));
                e0 = (u.x == 0xFFFFu) ? -1 : fbase + u.x;
                e1 = (u.y == 0xFFFFu) ? -1 : fbase + u.y;
                e2 = (u.z == 0xFFFFu) ? -1 : fbase + u.z;
                e3 = (u.w == 0xFFFFu) ? -1 : fbase + u.w;
            } else {
                if (x0 + 0 < BEV_W) { unsigned short u = g_grid16[base + x0 + 0]; e0 = (u == 0xFFFFu) ? -1 : fbase + u; }
                if (x0 + 1 < BEV_W) { unsigned short u = g_grid16[base + x0 + 1]; e1 = (u == 0xFFFFu) ? -1 : fbase + u; }
                if (x0 + 2 < BEV_W) { unsigned short u = g_grid16[base + x0 + 2]; e2 = (u == 0xFFFFu) ? -1 : fbase + u; }
                if (x0 + 3 < BEV_W) { unsigned short u = g_grid16[base + x0 + 3]; e3 = (u == 0xFFFFu) ? -1 : fbase + u; }
            }
            *reinterpret_cast<int4*>(&sring[slot * TILE_X + 4 * tid]) =
                make_int4(e0, e1, e2, e3);
            // all four negative <=> AND of sign bits set
            qring[slot * NQ + tid] = ((e0 & e1 & e2 & e3) < 0) ? 1 : 0;
        }
    };

    // ---- per-cell branchy gather: empty cell -> zero, no load ----
    auto gather = [&](int slot, float4* dst) {
#pragma unroll
        for (int i = 0; i < 4; i++) {
            int idx = sring[slot * TILE_X + i * 32 + rbase];
            float4 w = make_float4(0.f, 0.f, 0.f, 0.f);
            if (idx >= 0) {
                w = __ldg(feat4 + (size_t)idx * (CC / 4) + p);
            }
            dst[i] = w;
        }
    };

    float4 v[4];

    // ---- prologue ----
    load_idx(t0, 0);
    if (t0 + step < NT) load_idx(t0 + step, 1);
    __syncthreads();
    gather(0, v);

    int k = 0;
    for (int t = t0; t < NT; t += step, k++) {
        const int slot = k & 3;
        float* wb = vbuf + (size_t)(k & 1) * TILE_FLOATS;

        // Stage 1: STS only for cells in nonempty quads (zeros for empty cells
        // inside live quads come from the gather's zero registers).
#pragma unroll
        for (int i = 0; i < 4; i++) {
            int rl = i * 32 + rbase;
            if (!qring[slot * NQ + (rl >> 2)]) {
                int rx = rl ^ s4p;
                wb[(4 * p + 0) * ROW_STRIDE + rx] = v[i].x;
                wb[(4 * p + 1) * ROW_STRIDE + rx] = v[i].y;
                wb[(4 * p + 2) * ROW_STRIDE + rx] = v[i].z;
                wb[(4 * p + 3) * ROW_STRIDE + rx] = v[i].w;
            }
        }

        // Prefetch indices 2 tiles ahead; gather features for next tile
        // (LDGs stay in flight across the barrier + store phase).
        if (t + 2 * step < NT) load_idx(t + 2 * step, (k + 2) & 3);
        if (t + step < NT)     gather((k + 1) & 3, v);

        __syncthreads();

        // Stage 2: empty quad -> store zeros directly; else conflict-free
        // LDS.128 then coalesced streaming stores.
        {
            int r  = t >> 2;
            int b  = r / BEV_H;
            int y  = r - b * BEV_H;
            int x0 = (t & 3) * TILE_X + 4 * xq;
            if (x0 < BEV_W) {
                const bool qe = (qring[slot * NQ + xq] != 0);
                const float* rb = vbuf + (size_t)(k & 1) * TILE_FLOATS;
                size_t base = ((size_t)(b * CC + 4 * cq) * BEV_H + y) * BEV_W + x0;
#pragma unroll
                for (int j = 0; j < 4; j++) {
                    float4 o = make_float4(0.f, 0.f, 0.f, 0.f);
                    if (!qe) {
                        int c  = 4 * cq + j;
                        int s4 = ((c >> 3) & 7) << 2;
                        o = *reinterpret_cast<const float4*>(
                            &rb[c * ROW_STRIDE + ((4 * xq) ^ s4)]);
                    }
                    __stcs(reinterpret_cast<float4*>(out + base + (size_t)j * plane), o);
                }
            }
        }
        // Ring safety with one barrier: in window (bar k, bar k+1) readers use
        // slots {k, k+1, k+2} mod 4; the only writer uses slot k+3 mod 4.
    }
}

extern "C" void kernel_launch(void* const* d_in, const int* in_sizes, int n_in,
                              void* d_out, int out_size)
{
    const int*   coords = (const int*)d_in[0];    // (M, 3) int32 [b, y, x]
    const float* feat   = (const float*)d_in[1];  // (M, 64) float32
    float*       out    = (float*)d_out;          // (4, 64, 496, 432) float32

    const int M    = in_sizes[0] / 3;
    const int mper = M / BB;                      // batch-local id range (30000)

    void* grid_ptr = nullptr;
    cudaGetSymbolAddress(&grid_ptr, g_grid16);
    cudaMemsetAsync(grid_ptr, 0xFF, GRID_CELLS * sizeof(unsigned short));

    scatter_ids_kernel<<<(M + 255) / 256, 256>>>(coords, M, mper);

    static bool attr_set = false;
    if (!attr_set) {
        cudaFuncSetAttribute(gather_kernel,
                             cudaFuncAttributeMaxDynamicSharedMemorySize,
                             SMEM_BYTES);
        attr_set = true;
    }
    gather_kernel<<<GATHER_BLOCKS, 512, SMEM_BYTES>>>(feat, out, mper);
}

// round 16
// speedup vs baseline: 1.8169x; 1.0013x over previous
#include <cuda_runtime.h>
#include <cuda_bf16.h>

// PointPillars BEV scatter, inverted as a gather (uint16 grid, 4 blocks/SM).
//   1) cudaMemsetAsync grid16 to 0xFFFF (empty)
//   2) scatter batch-local pillar ids (16-bit) into grid16[(b*H+y)*W+x]
//   3) persistent gather blocks (4/SM, reg-capped to 32), single-buffered smem
//      tile, two barriers per tile, contiguous tile range per block with
//      division-free incremental output addressing. 4-slot idx+flag ring
//      prefetched 2 tiles ahead; all-empty 4-cell quads bypass smem both ways.
#define BEV_H 496
#define BEV_W 432
#define BB    4
#define CC    64
#define GRID_CELLS (BB * BEV_H * BEV_W)   // 857088
#define TILE_X 128
#define NQ     (TILE_X / 4)               // 32 quads per tile
#define NT     (BB * BEV_H * 4)           // 7936 tiles (4 x-tiles per row)
#define ROW_STRIDE 132
#define TILE_FLOATS (CC * ROW_STRIDE)     // 8448 floats = 33792 B
#define GATHER_BLOCKS 608                 // 4 per SM on 152-SM GB300
// 1 tile buffer + 4-slot idx ring + 4-slot quad-flag ring
#define SMEM_BYTES (TILE_FLOATS * 4 + 4 * TILE_X * 4 + 4 * NQ * 4)

__device__ unsigned short g_grid16[GRID_CELLS];   // 1.71 MB, L2-resident

__global__ void scatter_ids_kernel(const int* __restrict__ coords, int M, int mper) {
    int m = blockIdx.x * blockDim.x + threadIdx.x;
    if (m < M) {
        int b = coords[3 * m + 0];
        int y = coords[3 * m + 1];
        int x = coords[3 * m + 2];
        g_grid16[(b * BEV_H + y) * BEV_W + x] = (unsigned short)(m - b * mper);
    }
}

__global__ __launch_bounds__(512, 4) void gather_kernel(
    const float* __restrict__ feat, float* __restrict__ out, int mper)
{
    extern __shared__ __align__(16) float smem[];
    float* vbuf  = smem;                                  // [TILE_FLOATS]
    int*   sring = (int*)(smem + TILE_FLOATS);            // [4][TILE_X]
    int*   qring = (int*)(smem + TILE_FLOATS + 4 * TILE_X);  // [4][NQ] 1=empty

    const int tid   = threadIdx.x;
    const int p     = tid & 15;        // gather: channel quad
    const int rbase = tid >> 4;        // gather: cell sub-index (0..31)
    const int s4p   = (p >> 1) << 2;   // smem swizzle key for writes
    const int xq    = tid & 31;        // stage2: x quad
    const int cq    = tid >> 5;        // stage2: channel quad (0..15)

    // contiguous tile range for this block
    const int start = (int)(((long long)blockIdx.x * NT) / gridDim.x);
    const int endt  = (int)(((long long)(blockIdx.x + 1) * NT) / gridDim.x);

    const size_t plane = (size_t)BEV_H * BEV_W;
    const float4* feat4 = reinterpret_cast<const float4*>(feat);

    // ---- index + quad-flag loader: one warp; ushort4 grid reads ----
    auto load_idx = [&](int t, int slot) {
        if (tid < 32) {
            int r  = t >> 2;                   // combined b*H + y
            int b  = r / BEV_H;                // one div per tile, 1 warp only
            int x0 = (t & 3) * TILE_X + 4 * tid;
            int base = r * BEV_W;
            int fbase = b * mper;
            int e0 = -1, e1 = -1, e2 = -1, e3 = -1;
            if (x0 + 3 < BEV_W) {
                ushort4 u = __ldg(reinterpret_cast<const ushort4*>(&g_grid16[base + x0]));
                e0 = (u.x == 0xFFFFu) ? -1 : fbase + u.x;
                e1 = (u.y == 0xFFFFu) ? -1 : fbase + u.y;
                e2 = (u.z == 0xFFFFu) ? -1 : fbase + u.z;
                e3 = (u.w == 0xFFFFu) ? -1 : fbase + u.w;
            } else {
                if (x0 + 0 < BEV_W) { unsigned short u = g_grid16[base + x0 + 0]; e0 = (u == 0xFFFFu) ? -1 : fbase + u; }
                if (x0 + 1 < BEV_W) { unsigned short u = g_grid16[base + x0 + 1]; e1 = (u == 0xFFFFu) ? -1 : fbase + u; }
                if (x0 + 2 < BEV_W) { unsigned short u = g_grid16[base + x0 + 2]; e2 = (u == 0xFFFFu) ? -1 : fbase + u; }
                if (x0 + 3 < BEV_W) { unsigned short u = g_grid16[base + x0 + 3]; e3 = (u == 0xFFFFu) ? -1 : fbase + u; }
            }
            *reinterpret_cast<int4*>(&sring[slot * TILE_X + 4 * tid]) =
                make_int4(e0, e1, e2, e3);
            qring[slot * NQ + tid] = ((e0 & e1 & e2 & e3) < 0) ? 1 : 0;
        }
    };

    // ---- per-cell branchy gather: empty cell -> zero, no load ----
    auto gather = [&](int slot, float4* dst) {
#pragma unroll
        for (int i = 0; i < 4; i++) {
            int idx = sring[slot * TILE_X + i * 32 + rbase];
            float4 w = make_float4(0.f, 0.f, 0.f, 0.f);
            if (idx >= 0) {
                w = __ldg(feat4 + (size_t)idx * (CC / 4) + p);
            }
            dst[i] = w;
        }
    };

    float4 v[4];

    // ---- prologue ----
    load_idx(start, 0);
    if (start + 1 < NT) load_idx(start + 1, 1);
    __syncthreads();
    gather(0, v);

    // ---- incremental stage-2 coordinates (no div/mul in the loop) ----
    int xt, ycnt;
    size_t base2;
    {
        int r = start >> 2;
        int b = r / BEV_H;
        int y = r - b * BEV_H;
        xt   = start & 3;
        ycnt = y;
        base2 = ((size_t)(b * CC + 4 * cq) * BEV_H + y) * BEV_W
              + (size_t)xt * TILE_X + 4 * xq;
    }

    int k = 0;
    for (int t = start; t < endt; t++, k++) {
        const int slot = k & 3;

        // Stage 1: STS only for cells in nonempty quads.
#pragma unroll
        for (int i = 0; i < 4; i++) {
            int rl = i * 32 + rbase;
            if (!qring[slot * NQ + (rl >> 2)]) {
                int rx = rl ^ s4p;
                vbuf[(4 * p + 0) * ROW_STRIDE + rx] = v[i].x;
                vbuf[(4 * p + 1) * ROW_STRIDE + rx] = v[i].y;
                vbuf[(4 * p + 2) * ROW_STRIDE + rx] = v[i].z;
                vbuf[(4 * p + 3) * ROW_STRIDE + rx] = v[i].w;
            }
        }

        // Prefetch indices 2 tiles ahead; gather features for next tile.
        if (t + 2 < NT) load_idx(t + 2, (k + 2) & 3);
        if (t + 1 < NT) gather((k + 1) & 3, v);

        __syncthreads();

        // Stage 2: empty quad -> store zeros; else conflict-free LDS.128,
        // then coalesced streaming stores. x guard: only xt==3 is partial.
        if (xt < 3 || xq < 12) {           // 384 + 4*12 = 432
            const bool qe = (qring[slot * NQ + xq] != 0);
#pragma unroll
            for (int j = 0; j < 4; j++) {
                float4 o = make_float4(0.f, 0.f, 0.f, 0.f);
                if (!qe) {
                    int c  = 4 * cq + j;
                    int s4 = ((c >> 3) & 7) << 2;
                    o = *reinterpret_cast<const float4*>(
                        &vbuf[c * ROW_STRIDE + ((4 * xq) ^ s4)]);
                }
                __stcs(reinterpret_cast<float4*>(out + base2 + (size_t)j * plane), o);
            }
        }

        __syncthreads();   // protect vbuf before next iteration's STS

        // increment (xt, y, b) and base2 without division
        xt++;
        base2 += TILE_X;
        if (xt == 4) {
            xt = 0;
            base2 += (size_t)BEV_W - 4 * TILE_X;    // next y
            ycnt++;
            if (ycnt == BEV_H) {                    // next batch
                ycnt = 0;
                base2 += ((size_t)CC - 1) * plane;  // skip other 63 channel planes
            }
        }
    }
}

extern "C" void kernel_launch(void* const* d_in, const int* in_sizes, int n_in,
                              void* d_out, int out_size)
{
    const int*   coords = (const int*)d_in[0];    // (M, 3) int32 [b, y, x]
    const float* feat   = (const float*)d_in[1];  // (M, 64) float32
    float*       out    = (float*)d_out;          // (4, 64, 496, 432) float32

    const int M    = in_sizes[0] / 3;
    const int mper = M / BB;                      // batch-local id range (30000)

    void* grid_ptr = nullptr;
    cudaGetSymbolAddress(&grid_ptr, g_grid16);
    cudaMemsetAsync(grid_ptr, 0xFF, GRID_CELLS * sizeof(unsigned short));

    scatter_ids_kernel<<<(M + 255) / 256, 256>>>(coords, M, mper);

    static bool attr_set = false;
    if (!attr_set) {
        cudaFuncSetAttribute(gather_kernel,
                             cudaFuncAttributeMaxDynamicSharedMemorySize,
                             SMEM_BYTES);
        attr_set = true;
    }
    gather_kernel<<<GATHER_BLOCKS, 512, SMEM_BYTES>>>(feat, out, mper);
}